// round 11
// baseline (speedup 1.0000x reference)
#include <cuda_runtime.h>
#include <cuda_fp16.h>
#include <cuda_bf16.h>

#define Bb 16
#define Hh 12
#define Nn 784
#define NN (Nn * Nn)            // 614656
#define NN4 (NN / 4)            // 153664 float4 per batch
#define NN2 (NN / 2)            // 307328 half2 per batch
#define N4 (Nn / 4)             // 196 float4 per row
#define N2 (Nn / 2)             // 392 half2 per row
#define RPB 8                   // rows per norm block (= warps per block)

__device__ float g_max[Bb];                 // per-batch global max (atomicMax)
__device__ float g_rowmax[Bb * Nn];         // per-row max m_i
__device__ float g_rowsum[Bb * Nn];         // per-row sum of exp(x - m_i) (fp32)
__device__ float g_scale[Bb * Nn];          // per-row final scale exp(m_i - M)/S
__device__ __half2 g_exp[Bb * NN2];         // fp16 scratch: exp(x - m_i), 19.7 MB

__global__ void init_kernel() {
    int t = threadIdx.x;
    if (t < Bb) g_max[t] = 0.0f;
}

// One CTA per (b, i). 12 warps, warp h owns head h:
//  phase 1: load row m[b,h,i,:], fused rowsum during load, stage tile to SMEM.
//  phase 2: x[l] = sum_h tile[h][l]*rowsum[h] (regs); row max via SMEM atomics;
//           fp16 exp(x - m_i) to scratch; fp32 row sum via SMEM atomics.
__global__ __launch_bounds__(384) void agg_kernel(const float* __restrict__ m) {
    __shared__ float tiles[Hh * Nn];     // 37632 B
    __shared__ float rowsum[Hh];
    __shared__ int   s_max_i;            // atomicMax target (values >= 0)
    __shared__ float s_sum;              // atomicAdd target

    const int i = blockIdx.x;   // 0..783
    const int b = blockIdx.y;   // 0..15
    const int tid  = threadIdx.x;
    const int wid  = tid >> 5;  // head index 0..11
    const int lane = tid & 31;

    if (tid == 0) { s_max_i = 0; s_sum = 0.0f; }

    // ---- phase 1: load + fused per-head rowsum ----
    {
        const float4* __restrict__ src = (const float4*)m +
            ((size_t)(b * Hh + wid) * Nn + i) * (size_t)N4;
        float4* __restrict__ stile = (float4*)tiles + wid * N4;

        float s = 0.0f;
        #pragma unroll
        for (int k = 0; k < 6; k++) {
            float4 v = src[lane + 32 * k];
            stile[lane + 32 * k] = v;
            s += (v.x + v.y) + (v.z + v.w);
        }
        if (lane < 4) {                       // 196 = 6*32 + 4
            float4 v = src[192 + lane];
            stile[192 + lane] = v;
            s += (v.x + v.y) + (v.z + v.w);
        }
        #pragma unroll
        for (int off = 16; off > 0; off >>= 1)
            s += __shfl_xor_sync(0xFFFFFFFFu, s, off);
        if (lane == 0) rowsum[wid] = s;
    }
    __syncthreads();                          // barrier 1

    float rs[Hh];
    #pragma unroll
    for (int h = 0; h < Hh; h++) rs[h] = rowsum[h];

    // ---- phase 2a: weighted head-sum into registers ----
    const bool has2 = (tid < N2 - 384);       // tid < 8
    float2 v0, v1 = make_float2(0.f, 0.f);
    float lmax = 0.0f;                        // all values >= 0
    {
        float2 acc = make_float2(0.f, 0.f);
        #pragma unroll
        for (int h = 0; h < Hh; h++) {
            float2 t = ((const float2*)tiles)[h * N2 + tid];
            acc.x += t.x * rs[h];
            acc.y += t.y * rs[h];
        }
        v0 = acc;
        lmax = fmaxf(acc.x, acc.y);
    }
    if (has2) {
        float2 acc = make_float2(0.f, 0.f);
        const int c = tid + 384;
        #pragma unroll
        for (int h = 0; h < Hh; h++) {
            float2 t = ((const float2*)tiles)[h * N2 + c];
            acc.x += t.x * rs[h];
            acc.y += t.y * rs[h];
        }
        v1 = acc;
        lmax = fmaxf(lmax, fmaxf(acc.x, acc.y));
    }

    // ---- row max: warp shfl-tree + one SMEM atomic per warp ----
    #pragma unroll
    for (int off = 16; off > 0; off >>= 1)
        lmax = fmaxf(lmax, __shfl_xor_sync(0xFFFFFFFFu, lmax, off));
    if (lane == 0) atomicMax(&s_max_i, __float_as_int(lmax));
    __syncthreads();                          // barrier 2
    const float m_i = __int_as_float(s_max_i);

    // overlap the global atomic with the exp/store phase
    if (tid == 0) {
        g_rowmax[b * Nn + i] = m_i;
        atomicMax((int*)&g_max[b], __float_as_int(m_i));
    }

    // ---- exp, fp16 store, fp32 row sum via SMEM atomics ----
    __half2* __restrict__ dst = g_exp + (size_t)b * NN2 + (size_t)i * N2;
    float lsum;
    {
        float ex = __expf(v0.x - m_i);
        float ey = __expf(v0.y - m_i);
        dst[tid] = __floats2half2_rn(ex, ey);
        lsum = ex + ey;
    }
    if (has2) {
        float ex = __expf(v1.x - m_i);
        float ey = __expf(v1.y - m_i);
        dst[tid + 384] = __floats2half2_rn(ex, ey);
        lsum += ex + ey;
    }
    #pragma unroll
    for (int off = 16; off > 0; off >>= 1)
        lsum += __shfl_xor_sync(0xFFFFFFFFu, lsum, off);
    if (lane == 0) atomicAdd(&s_sum, lsum);
    __syncthreads();                          // barrier 3
    if (tid == 0)
        g_rowsum[b * Nn + i] = s_sum;
}

// One block per batch: S = sum_i s_i * exp(m_i - M); scale_i = exp(m_i - M)/S.
__global__ __launch_bounds__(256) void mid_kernel() {
    __shared__ float wred[8];
    __shared__ float s_inv;
    const int b = blockIdx.x;
    const float M = g_max[b];
    const int tid = threadIdx.x;

    float s = 0.0f;
    for (int i = tid; i < Nn; i += 256)
        s += g_rowsum[b * Nn + i] * __expf(g_rowmax[b * Nn + i] - M);
    #pragma unroll
    for (int off = 16; off > 0; off >>= 1)
        s += __shfl_xor_sync(0xFFFFFFFFu, s, off);
    const int wid = tid >> 5, lane = tid & 31;
    if (lane == 0) wred[wid] = s;
    __syncthreads();
    if (tid == 0) {
        float t = wred[0];
        #pragma unroll
        for (int w = 1; w < 8; w++) t += wred[w];
        s_inv = 1.0f / t;
    }
    __syncthreads();
    const float inv = s_inv;
    for (int i = tid; i < Nn; i += 256)
        g_scale[b * Nn + i] = __expf(g_rowmax[b * Nn + i] - M) * inv;
}

// Warp-per-row normalize: block = 8 warps = 8 rows, grid (98, 16).
// Row = 196 float4: 6 full warp iterations + 4-lane remainder. Division-free.
__global__ __launch_bounds__(256) void norm_kernel(float* __restrict__ out) {
    const int b = blockIdx.y;
    const int wid  = threadIdx.x >> 5;        // 0..7
    const int lane = threadIdx.x & 31;
    const int r = blockIdx.x * RPB + wid;     // row index

    const float sc = g_scale[b * Nn + r];
    const uint2* __restrict__ src =
        (const uint2*)(g_exp + (size_t)b * NN2 + (size_t)r * N2);
    float4* __restrict__ p = (float4*)out + (size_t)b * NN4 + (size_t)r * N4;

    #pragma unroll
    for (int k = 0; k < 6; k++) {
        const int c = lane + 32 * k;
        uint2 u = src[c];
        float2 a = __half22float2(*(const __half2*)&u.x);
        float2 d = __half22float2(*(const __half2*)&u.y);
        p[c] = make_float4(a.x * sc, a.y * sc, d.x * sc, d.y * sc);
    }
    if (lane < 4) {                           // 196 = 6*32 + 4
        const int c = 192 + lane;
        uint2 u = src[c];
        float2 a = __half22float2(*(const __half2*)&u.x);
        float2 d = __half22float2(*(const __half2*)&u.y);
        p[c] = make_float4(a.x * sc, a.y * sc, d.x * sc, d.y * sc);
    }
}

extern "C" void kernel_launch(void* const* d_in, const int* in_sizes, int n_in,
                              void* d_out, int out_size) {
    const float* m = (const float*)d_in[0];
    float* out = (float*)d_out;

    init_kernel<<<1, 32>>>();

    dim3 g1(Nn, Bb);            // 784 x 16 CTAs
    agg_kernel<<<g1, 384>>>(m);

    mid_kernel<<<Bb, 256>>>();

    dim3 g3(Nn / RPB, Bb);      // 98 x 16 blocks, 8 rows each
    norm_kernel<<<g3, 256>>>(out);
}

// round 14
// speedup vs baseline: 1.0078x; 1.0078x over previous
#include <cuda_runtime.h>
#include <cuda_fp16.h>
#include <cuda_bf16.h>

#define Bb 16
#define Hh 12
#define Nn 784
#define NN (Nn * Nn)            // 614656
#define NN4 (NN / 4)            // 153664 float4 per batch
#define NN2 (NN / 2)            // 307328 half2 per batch
#define N4 (Nn / 4)             // 196 float4 per row
#define N2 (Nn / 2)             // 392 half2 per row
#define RPB 16                  // rows per norm block (= warps per block)

__device__ float g_max[Bb];                 // per-batch global max (atomicMax)
__device__ float g_rowmax[Bb * Nn];         // per-row max m_i
__device__ float g_rowsum[Bb * Nn];         // per-row sum of exp(x - m_i) (fp32)
__device__ float g_scale[Bb * Nn];          // per-row final scale exp(m_i - M)/S
__device__ __half2 g_exp[Bb * NN2];         // fp16 scratch: exp(x - m_i), 19.7 MB

__global__ void init_kernel() {
    int t = threadIdx.x;
    if (t < Bb) g_max[t] = 0.0f;
}

// One CTA per (b, i). 12 warps, warp h owns head h:
//  phase 1: load row m[b,h,i,:], fused rowsum during load, stage tile to SMEM.
//  phase 2: x[l] = sum_h tile[h][l]*rowsum[h] (regs), row max m_i,
//           fp16 exp(x - m_i) to scratch, fp32 row sum s_i, atomicMax.
__global__ __launch_bounds__(384) void agg_kernel(const float* __restrict__ m) {
    __shared__ float tiles[Hh * Nn];     // 37632 B
    __shared__ float rowsum[Hh];
    __shared__ float wred[12];
    __shared__ float s_bcast;

    const int i = blockIdx.x;   // 0..783
    const int b = blockIdx.y;   // 0..15
    const int tid  = threadIdx.x;
    const int wid  = tid >> 5;  // head index 0..11
    const int lane = tid & 31;

    // ---- phase 1: load + fused per-head rowsum ----
    {
        const float4* __restrict__ src = (const float4*)m +
            ((size_t)(b * Hh + wid) * Nn + i) * (size_t)N4;
        float4* __restrict__ stile = (float4*)tiles + wid * N4;

        float s = 0.0f;
        #pragma unroll
        for (int k = 0; k < 6; k++) {
            float4 v = src[lane + 32 * k];
            stile[lane + 32 * k] = v;
            s += (v.x + v.y) + (v.z + v.w);
        }
        if (lane < 4) {                       // 196 = 6*32 + 4
            float4 v = src[192 + lane];
            stile[192 + lane] = v;
            s += (v.x + v.y) + (v.z + v.w);
        }
        #pragma unroll
        for (int off = 16; off > 0; off >>= 1)
            s += __shfl_xor_sync(0xFFFFFFFFu, s, off);
        if (lane == 0) rowsum[wid] = s;
    }
    __syncthreads();

    float rs[Hh];
    #pragma unroll
    for (int h = 0; h < Hh; h++) rs[h] = rowsum[h];

    // ---- phase 2a: weighted head-sum into registers ----
    const bool has2 = (tid < N2 - 384);       // tid < 8
    float2 v0, v1 = make_float2(0.f, 0.f);
    float lmax = 0.0f;                        // all values >= 0
    {
        float2 acc = make_float2(0.f, 0.f);
        #pragma unroll
        for (int h = 0; h < Hh; h++) {
            float2 t = ((const float2*)tiles)[h * N2 + tid];
            acc.x += t.x * rs[h];
            acc.y += t.y * rs[h];
        }
        v0 = acc;
        lmax = fmaxf(acc.x, acc.y);
    }
    if (has2) {
        float2 acc = make_float2(0.f, 0.f);
        const int c = tid + 384;
        #pragma unroll
        for (int h = 0; h < Hh; h++) {
            float2 t = ((const float2*)tiles)[h * N2 + c];
            acc.x += t.x * rs[h];
            acc.y += t.y * rs[h];
        }
        v1 = acc;
        lmax = fmaxf(lmax, fmaxf(acc.x, acc.y));
    }

    // ---- row max reduce (shfl-tree + SMEM table) ----
    #pragma unroll
    for (int off = 16; off > 0; off >>= 1)
        lmax = fmaxf(lmax, __shfl_xor_sync(0xFFFFFFFFu, lmax, off));
    if (lane == 0) wred[wid] = lmax;
    __syncthreads();
    if (tid == 0) {
        float mx = wred[0];
        #pragma unroll
        for (int w = 1; w < 12; w++) mx = fmaxf(mx, wred[w]);
        s_bcast = mx;
    }
    __syncthreads();
    const float m_i = s_bcast;

    // ---- exp, fp16 store, fp32 row sum ----
    __half2* __restrict__ dst = g_exp + (size_t)b * NN2 + (size_t)i * N2;
    float lsum;
    {
        float ex = __expf(v0.x - m_i);
        float ey = __expf(v0.y - m_i);
        dst[tid] = __floats2half2_rn(ex, ey);
        lsum = ex + ey;
    }
    if (has2) {
        float ex = __expf(v1.x - m_i);
        float ey = __expf(v1.y - m_i);
        dst[tid + 384] = __floats2half2_rn(ex, ey);
        lsum += ex + ey;
    }
    #pragma unroll
    for (int off = 16; off > 0; off >>= 1)
        lsum += __shfl_xor_sync(0xFFFFFFFFu, lsum, off);
    if (lane == 0) wred[wid] = lsum;
    __syncthreads();
    if (tid == 0) {
        float ssum = wred[0];
        #pragma unroll
        for (int w = 1; w < 12; w++) ssum += wred[w];
        const int r = b * Nn + i;
        g_rowmax[r] = m_i;
        g_rowsum[r] = ssum;
        atomicMax((int*)&g_max[b], __float_as_int(m_i));
    }
}

// One block per batch: S = sum_i s_i * exp(m_i - M); scale_i = exp(m_i - M)/S.
__global__ __launch_bounds__(256) void mid_kernel() {
    __shared__ float wred[8];
    __shared__ float s_inv;
    const int b = blockIdx.x;
    const float M = g_max[b];
    const int tid = threadIdx.x;

    float s = 0.0f;
    for (int i = tid; i < Nn; i += 256)
        s += g_rowsum[b * Nn + i] * __expf(g_rowmax[b * Nn + i] - M);
    #pragma unroll
    for (int off = 16; off > 0; off >>= 1)
        s += __shfl_xor_sync(0xFFFFFFFFu, s, off);
    const int wid = tid >> 5, lane = tid & 31;
    if (lane == 0) wred[wid] = s;
    __syncthreads();
    if (tid == 0) {
        float t = wred[0];
        #pragma unroll
        for (int w = 1; w < 8; w++) t += wred[w];
        s_inv = 1.0f / t;
    }
    __syncthreads();
    const float inv = s_inv;
    for (int i = tid; i < Nn; i += 256)
        g_scale[b * Nn + i] = __expf(g_rowmax[b * Nn + i] - M) * inv;
}

// Warp-per-row normalize: block = 16 warps = 16 rows, grid (49, 16).
// Row = 196 float4: 6 full warp iterations + 4-lane remainder. Division-free.
__global__ __launch_bounds__(512) void norm_kernel(float* __restrict__ out) {
    const int b = blockIdx.y;
    const int wid  = threadIdx.x >> 5;        // 0..15
    const int lane = threadIdx.x & 31;
    const int r = blockIdx.x * RPB + wid;     // row index

    const float sc = g_scale[b * Nn + r];
    const uint2* __restrict__ src =
        (const uint2*)(g_exp + (size_t)b * NN2 + (size_t)r * N2);
    float4* __restrict__ p = (float4*)out + (size_t)b * NN4 + (size_t)r * N4;

    #pragma unroll
    for (int k = 0; k < 6; k++) {
        const int c = lane + 32 * k;
        uint2 u = src[c];
        float2 a = __half22float2(*(const __half2*)&u.x);
        float2 d = __half22float2(*(const __half2*)&u.y);
        p[c] = make_float4(a.x * sc, a.y * sc, d.x * sc, d.y * sc);
    }
    if (lane < 4) {                           // 196 = 6*32 + 4
        const int c = 192 + lane;
        uint2 u = src[c];
        float2 a = __half22float2(*(const __half2*)&u.x);
        float2 d = __half22float2(*(const __half2*)&u.y);
        p[c] = make_float4(a.x * sc, a.y * sc, d.x * sc, d.y * sc);
    }
}

extern "C" void kernel_launch(void* const* d_in, const int* in_sizes, int n_in,
                              void* d_out, int out_size) {
    const float* m = (const float*)d_in[0];
    float* out = (float*)d_out;

    init_kernel<<<1, 32>>>();

    dim3 g1(Nn, Bb);            // 784 x 16 CTAs
    agg_kernel<<<g1, 384>>>(m);

    mid_kernel<<<Bb, 256>>>();

    dim3 g3(Nn / RPB, Bb);      // 49 x 16 blocks, 16 rows each
    norm_kernel<<<g3, 512>>>(out);
}

// round 15
// speedup vs baseline: 1.3692x; 1.3585x over previous
#include <cuda_runtime.h>
#include <cuda_fp16.h>
#include <cuda_bf16.h>

#define Bb 16
#define Hh 12
#define Nn 784
#define NN (Nn * Nn)            // 614656
#define NN4 (NN / 4)            // 153664 float4 per batch
#define NN2 (NN / 2)            // 307328 half2 per batch
#define N4 (Nn / 4)             // 196 float4 per row
#define N2 (Nn / 2)             // 392 half2 per row
#define RPB 16                  // rows per norm block (= warps per block)

__device__ float g_rowmax[Bb * Nn];         // per-row max m_i
__device__ float g_rowsum[Bb * Nn];         // per-row sum of exp(x - m_i) (fp32)
__device__ float g_scale[Bb * Nn];          // per-row final scale exp(m_i - M)/S
__device__ __half2 g_exp[Bb * NN2];         // fp16 scratch: exp(x - m_i), 19.7 MB

// One CTA per (b, i). 12 warps, warp h owns head h:
//  phase 1: load row m[b,h,i,:] with streaming hint (read-once), fused rowsum,
//           stage tile to SMEM.
//  phase 2: x[l] = sum_h tile[h][l]*rowsum[h] (regs), row max m_i,
//           fp16 exp(x - m_i) to scratch, fp32 row sum s_i.
__global__ __launch_bounds__(384) void agg_kernel(const float* __restrict__ m) {
    __shared__ float tiles[Hh * Nn];     // 37632 B
    __shared__ float rowsum[Hh];
    __shared__ float wred[12];
    __shared__ float s_bcast;

    const int i = blockIdx.x;   // 0..783
    const int b = blockIdx.y;   // 0..15
    const int tid  = threadIdx.x;
    const int wid  = tid >> 5;  // head index 0..11
    const int lane = tid & 31;

    // ---- phase 1: load (evict-first) + fused per-head rowsum ----
    {
        const float4* __restrict__ src = (const float4*)m +
            ((size_t)(b * Hh + wid) * Nn + i) * (size_t)N4;
        float4* __restrict__ stile = (float4*)tiles + wid * N4;

        float s = 0.0f;
        #pragma unroll
        for (int k = 0; k < 6; k++) {
            float4 v = __ldcs(src + lane + 32 * k);
            stile[lane + 32 * k] = v;
            s += (v.x + v.y) + (v.z + v.w);
        }
        if (lane < 4) {                       // 196 = 6*32 + 4
            float4 v = __ldcs(src + 192 + lane);
            stile[192 + lane] = v;
            s += (v.x + v.y) + (v.z + v.w);
        }
        #pragma unroll
        for (int off = 16; off > 0; off >>= 1)
            s += __shfl_xor_sync(0xFFFFFFFFu, s, off);
        if (lane == 0) rowsum[wid] = s;
    }
    __syncthreads();

    float rs[Hh];
    #pragma unroll
    for (int h = 0; h < Hh; h++) rs[h] = rowsum[h];

    // ---- phase 2a: weighted head-sum into registers ----
    const bool has2 = (tid < N2 - 384);       // tid < 8
    float2 v0, v1 = make_float2(0.f, 0.f);
    float lmax = 0.0f;                        // all values >= 0
    {
        float2 acc = make_float2(0.f, 0.f);
        #pragma unroll
        for (int h = 0; h < Hh; h++) {
            float2 t = ((const float2*)tiles)[h * N2 + tid];
            acc.x += t.x * rs[h];
            acc.y += t.y * rs[h];
        }
        v0 = acc;
        lmax = fmaxf(acc.x, acc.y);
    }
    if (has2) {
        float2 acc = make_float2(0.f, 0.f);
        const int c = tid + 384;
        #pragma unroll
        for (int h = 0; h < Hh; h++) {
            float2 t = ((const float2*)tiles)[h * N2 + c];
            acc.x += t.x * rs[h];
            acc.y += t.y * rs[h];
        }
        v1 = acc;
        lmax = fmaxf(lmax, fmaxf(acc.x, acc.y));
    }

    // ---- row max reduce (shfl-tree + SMEM table) ----
    #pragma unroll
    for (int off = 16; off > 0; off >>= 1)
        lmax = fmaxf(lmax, __shfl_xor_sync(0xFFFFFFFFu, lmax, off));
    if (lane == 0) wred[wid] = lmax;
    __syncthreads();
    if (tid == 0) {
        float mx = wred[0];
        #pragma unroll
        for (int w = 1; w < 12; w++) mx = fmaxf(mx, wred[w]);
        s_bcast = mx;
    }
    __syncthreads();
    const float m_i = s_bcast;

    // overlap rowmax write with the exp/store phase
    if (tid == 0) g_rowmax[b * Nn + i] = m_i;

    // ---- exp, fp16 store, fp32 row sum ----
    __half2* __restrict__ dst = g_exp + (size_t)b * NN2 + (size_t)i * N2;
    float lsum;
    {
        float ex = __expf(v0.x - m_i);
        float ey = __expf(v0.y - m_i);
        dst[tid] = __floats2half2_rn(ex, ey);
        lsum = ex + ey;
    }
    if (has2) {
        float ex = __expf(v1.x - m_i);
        float ey = __expf(v1.y - m_i);
        dst[tid + 384] = __floats2half2_rn(ex, ey);
        lsum += ex + ey;
    }
    #pragma unroll
    for (int off = 16; off > 0; off >>= 1)
        lsum += __shfl_xor_sync(0xFFFFFFFFu, lsum, off);
    if (lane == 0) wred[wid] = lsum;
    __syncthreads();
    if (tid == 0) {
        float ssum = wred[0];
        #pragma unroll
        for (int w = 1; w < 12; w++) ssum += wred[w];
        g_rowsum[b * Nn + i] = ssum;
    }
}

// One block per batch. Computes M = max_i m_i itself (no global atomic, no
// init kernel), then S = sum_i s_i * exp(m_i - M), then scale_i.
__global__ __launch_bounds__(256) void mid_kernel() {
    __shared__ float wred[8];
    __shared__ float s_bc;
    const int b = blockIdx.x;
    const int tid = threadIdx.x;
    const int wid = tid >> 5, lane = tid & 31;

    // ---- M = max_i rowmax ----
    float mx = 0.0f;
    for (int i = tid; i < Nn; i += 256)
        mx = fmaxf(mx, g_rowmax[b * Nn + i]);
    #pragma unroll
    for (int off = 16; off > 0; off >>= 1)
        mx = fmaxf(mx, __shfl_xor_sync(0xFFFFFFFFu, mx, off));
    if (lane == 0) wred[wid] = mx;
    __syncthreads();
    if (tid == 0) {
        float t = wred[0];
        #pragma unroll
        for (int w = 1; w < 8; w++) t = fmaxf(t, wred[w]);
        s_bc = t;
    }
    __syncthreads();
    const float M = s_bc;

    // ---- S = sum_i s_i * exp(m_i - M) ----
    float s = 0.0f;
    for (int i = tid; i < Nn; i += 256)
        s += g_rowsum[b * Nn + i] * __expf(g_rowmax[b * Nn + i] - M);
    #pragma unroll
    for (int off = 16; off > 0; off >>= 1)
        s += __shfl_xor_sync(0xFFFFFFFFu, s, off);
    if (lane == 0) wred[wid] = s;
    __syncthreads();
    if (tid == 0) {
        float t = wred[0];
        #pragma unroll
        for (int w = 1; w < 8; w++) t += wred[w];
        s_bc = 1.0f / t;
    }
    __syncthreads();
    const float inv = s_bc;

    for (int i = tid; i < Nn; i += 256)
        g_scale[b * Nn + i] = __expf(g_rowmax[b * Nn + i] - M) * inv;
}

// Warp-per-row normalize: block = 16 warps = 16 rows, grid (49, 16).
// Row = 196 float4: 6 full warp iterations + 4-lane remainder. Division-free.
// Scratch read is read-once (__ldcs); output write is write-once (__stcs).
__global__ __launch_bounds__(512) void norm_kernel(float* __restrict__ out) {
    const int b = blockIdx.y;
    const int wid  = threadIdx.x >> 5;        // 0..15
    const int lane = threadIdx.x & 31;
    const int r = blockIdx.x * RPB + wid;     // row index

    const float sc = g_scale[b * Nn + r];
    const uint2* __restrict__ src =
        (const uint2*)(g_exp + (size_t)b * NN2 + (size_t)r * N2);
    float4* __restrict__ p = (float4*)out + (size_t)b * NN4 + (size_t)r * N4;

    #pragma unroll
    for (int k = 0; k < 6; k++) {
        const int c = lane + 32 * k;
        uint2 u = __ldcs(src + c);
        float2 a = __half22float2(*(const __half2*)&u.x);
        float2 d = __half22float2(*(const __half2*)&u.y);
        __stcs(p + c, make_float4(a.x * sc, a.y * sc, d.x * sc, d.y * sc));
    }
    if (lane < 4) {                           // 196 = 6*32 + 4
        const int c = 192 + lane;
        uint2 u = __ldcs(src + c);
        float2 a = __half22float2(*(const __half2*)&u.x);
        float2 d = __half22float2(*(const __half2*)&u.y);
        __stcs(p + c, make_float4(a.x * sc, a.y * sc, d.x * sc, d.y * sc));
    }
}

extern "C" void kernel_launch(void* const* d_in, const int* in_sizes, int n_in,
                              void* d_out, int out_size) {
    const float* m = (const float*)d_in[0];
    float* out = (float*)d_out;

    dim3 g1(Nn, Bb);            // 784 x 16 CTAs
    agg_kernel<<<g1, 384>>>(m);

    mid_kernel<<<Bb, 256>>>();

    dim3 g3(Nn / RPB, Bb);      // 49 x 16 blocks, 16 rows each
    norm_kernel<<<g3, 512>>>(out);
}

// round 17
// speedup vs baseline: 1.3781x; 1.0065x over previous
#include <cuda_runtime.h>
#include <cuda_fp16.h>
#include <cuda_bf16.h>

#define Bb 16
#define Hh 12
#define Nn 784
#define NN (Nn * Nn)            // 614656
#define NN4 (NN / 4)            // 153664 float4 per batch
#define NN2 (NN / 2)            // 307328 half2 per batch
#define N4 (Nn / 4)             // 196 float4 per row
#define N2 (Nn / 2)             // 392 half2 per row
#define RPB 16                  // rows per norm block (= warps per block)

__device__ float g_rowmax[Bb * Nn];         // per-row max m_i
__device__ float g_rowsum[Bb * Nn];         // per-row sum of exp(x - m_i) (fp32)
__device__ float g_scale[Bb * Nn];          // per-row final scale exp(m_i - M)/S
__device__ __half2 g_exp[Bb * NN2];         // fp16 scratch: exp(x - m_i), 19.7 MB

// cp.async 16B global->shared, L2-only (.cg), no register staging.
__device__ __forceinline__ void cp_async16(void* smem_dst, const void* gmem_src) {
    unsigned sa = (unsigned)__cvta_generic_to_shared(smem_dst);
    asm volatile("cp.async.cg.shared.global [%0], [%1], 16;\n"
                 :: "r"(sa), "l"(gmem_src));
}
__device__ __forceinline__ void cp_async_commit_wait_all() {
    asm volatile("cp.async.commit_group;\n");
    asm volatile("cp.async.wait_group 0;\n");
}

// One CTA per (b, i). 12 warps, warp h owns head h:
//  phase 1: cp.async row m[b,h,i,:] -> SMEM (register-free, deep MLP),
//           then per-head rowsum from SMEM.
//  phase 2: x[l] = sum_h tile[h][l]*rowsum[h] (regs), row max m_i,
//           fp16 exp(x - m_i) to scratch, fp32 row sum s_i.
__global__ __launch_bounds__(384) void agg_kernel(const float* __restrict__ m) {
    __shared__ float tiles[Hh * Nn];     // 37632 B
    __shared__ float rowsum[Hh];
    __shared__ float wred[12];
    __shared__ float s_bcast;

    const int i = blockIdx.x;   // 0..783
    const int b = blockIdx.y;   // 0..15
    const int tid  = threadIdx.x;
    const int wid  = tid >> 5;  // head index 0..11
    const int lane = tid & 31;

    // ---- phase 1a: issue all async copies (no register staging) ----
    {
        const float4* __restrict__ src = (const float4*)m +
            ((size_t)(b * Hh + wid) * Nn + i) * (size_t)N4;
        float4* __restrict__ stile = (float4*)tiles + wid * N4;

        #pragma unroll
        for (int k = 0; k < 6; k++)
            cp_async16(stile + lane + 32 * k, src + lane + 32 * k);
        if (lane < 4)                         // 196 = 6*32 + 4
            cp_async16(stile + 192 + lane, src + 192 + lane);
        cp_async_commit_wait_all();
    }
    __syncthreads();

    // ---- phase 1b: per-head rowsum from SMEM (warp wid -> head wid) ----
    {
        const float4* __restrict__ stile = (const float4*)tiles + wid * N4;
        float s = 0.0f;
        #pragma unroll
        for (int k = 0; k < 6; k++) {
            float4 v = stile[lane + 32 * k];
            s += (v.x + v.y) + (v.z + v.w);
        }
        if (lane < 4) {
            float4 v = stile[192 + lane];
            s += (v.x + v.y) + (v.z + v.w);
        }
        #pragma unroll
        for (int off = 16; off > 0; off >>= 1)
            s += __shfl_xor_sync(0xFFFFFFFFu, s, off);
        if (lane == 0) rowsum[wid] = s;
    }
    __syncthreads();

    float rs[Hh];
    #pragma unroll
    for (int h = 0; h < Hh; h++) rs[h] = rowsum[h];

    // ---- phase 2a: weighted head-sum into registers ----
    const bool has2 = (tid < N2 - 384);       // tid < 8
    float2 v0, v1 = make_float2(0.f, 0.f);
    float lmax = 0.0f;                        // all values >= 0
    {
        float2 acc = make_float2(0.f, 0.f);
        #pragma unroll
        for (int h = 0; h < Hh; h++) {
            float2 t = ((const float2*)tiles)[h * N2 + tid];
            acc.x += t.x * rs[h];
            acc.y += t.y * rs[h];
        }
        v0 = acc;
        lmax = fmaxf(acc.x, acc.y);
    }
    if (has2) {
        float2 acc = make_float2(0.f, 0.f);
        const int c = tid + 384;
        #pragma unroll
        for (int h = 0; h < Hh; h++) {
            float2 t = ((const float2*)tiles)[h * N2 + c];
            acc.x += t.x * rs[h];
            acc.y += t.y * rs[h];
        }
        v1 = acc;
        lmax = fmaxf(lmax, fmaxf(acc.x, acc.y));
    }

    // ---- row max reduce (shfl-tree + SMEM table) ----
    #pragma unroll
    for (int off = 16; off > 0; off >>= 1)
        lmax = fmaxf(lmax, __shfl_xor_sync(0xFFFFFFFFu, lmax, off));
    if (lane == 0) wred[wid] = lmax;
    __syncthreads();
    if (tid == 0) {
        float mx = wred[0];
        #pragma unroll
        for (int w = 1; w < 12; w++) mx = fmaxf(mx, wred[w]);
        s_bcast = mx;
    }
    __syncthreads();
    const float m_i = s_bcast;

    if (tid == 0) g_rowmax[b * Nn + i] = m_i;   // overlaps with exp phase

    // ---- exp, fp16 store, fp32 row sum ----
    __half2* __restrict__ dst = g_exp + (size_t)b * NN2 + (size_t)i * N2;
    float lsum;
    {
        float ex = __expf(v0.x - m_i);
        float ey = __expf(v0.y - m_i);
        dst[tid] = __floats2half2_rn(ex, ey);
        lsum = ex + ey;
    }
    if (has2) {
        float ex = __expf(v1.x - m_i);
        float ey = __expf(v1.y - m_i);
        dst[tid + 384] = __floats2half2_rn(ex, ey);
        lsum += ex + ey;
    }
    #pragma unroll
    for (int off = 16; off > 0; off >>= 1)
        lsum += __shfl_xor_sync(0xFFFFFFFFu, lsum, off);
    if (lane == 0) wred[wid] = lsum;
    __syncthreads();
    if (tid == 0) {
        float ssum = wred[0];
        #pragma unroll
        for (int w = 1; w < 12; w++) ssum += wred[w];
        g_rowsum[b * Nn + i] = ssum;
    }
}

// One block per batch. Computes M = max_i m_i itself, then
// S = sum_i s_i * exp(m_i - M), then scale_i = exp(m_i - M)/S.
__global__ __launch_bounds__(256) void mid_kernel() {
    __shared__ float wred[8];
    __shared__ float s_bc;
    const int b = blockIdx.x;
    const int tid = threadIdx.x;
    const int wid = tid >> 5, lane = tid & 31;

    // ---- M = max_i rowmax ----
    float mx = 0.0f;
    for (int i = tid; i < Nn; i += 256)
        mx = fmaxf(mx, g_rowmax[b * Nn + i]);
    #pragma unroll
    for (int off = 16; off > 0; off >>= 1)
        mx = fmaxf(mx, __shfl_xor_sync(0xFFFFFFFFu, mx, off));
    if (lane == 0) wred[wid] = mx;
    __syncthreads();
    if (tid == 0) {
        float t = wred[0];
        #pragma unroll
        for (int w = 1; w < 8; w++) t = fmaxf(t, wred[w]);
        s_bc = t;
    }
    __syncthreads();
    const float M = s_bc;

    // ---- S = sum_i s_i * exp(m_i - M) ----
    float s = 0.0f;
    for (int i = tid; i < Nn; i += 256)
        s += g_rowsum[b * Nn + i] * __expf(g_rowmax[b * Nn + i] - M);
    #pragma unroll
    for (int off = 16; off > 0; off >>= 1)
        s += __shfl_xor_sync(0xFFFFFFFFu, s, off);
    if (lane == 0) wred[wid] = s;
    __syncthreads();
    if (tid == 0) {
        float t = wred[0];
        #pragma unroll
        for (int w = 1; w < 8; w++) t += wred[w];
        s_bc = 1.0f / t;
    }
    __syncthreads();
    const float inv = s_bc;

    for (int i = tid; i < Nn; i += 256)
        g_scale[b * Nn + i] = __expf(g_rowmax[b * Nn + i] - M) * inv;
}

// Warp-per-row normalize: block = 16 warps = 16 rows, grid (49, 16).
// Row = 196 float4: 6 full warp iterations + 4-lane remainder. Division-free.
__global__ __launch_bounds__(512) void norm_kernel(float* __restrict__ out) {
    const int b = blockIdx.y;
    const int wid  = threadIdx.x >> 5;        // 0..15
    const int lane = threadIdx.x & 31;
    const int r = blockIdx.x * RPB + wid;     // row index

    const float sc = g_scale[b * Nn + r];
    const uint2* __restrict__ src =
        (const uint2*)(g_exp + (size_t)b * NN2 + (size_t)r * N2);
    float4* __restrict__ p = (float4*)out + (size_t)b * NN4 + (size_t)r * N4;

    #pragma unroll
    for (int k = 0; k < 6; k++) {
        const int c = lane + 32 * k;
        uint2 u = __ldcs(src + c);
        float2 a = __half22float2(*(const __half2*)&u.x);
        float2 d = __half22float2(*(const __half2*)&u.y);
        __stcs(p + c, make_float4(a.x * sc, a.y * sc, d.x * sc, d.y * sc));
    }
    if (lane < 4) {                           // 196 = 6*32 + 4
        const int c = 192 + lane;
        uint2 u = __ldcs(src + c);
        float2 a = __half22float2(*(const __half2*)&u.x);
        float2 d = __half22float2(*(const __half2*)&u.y);
        __stcs(p + c, make_float4(a.x * sc, a.y * sc, d.x * sc, d.y * sc));
    }
}

extern "C" void kernel_launch(void* const* d_in, const int* in_sizes, int n_in,
                              void* d_out, int out_size) {
    const float* m = (const float*)d_in[0];
    float* out = (float*)d_out;

    dim3 g1(Nn, Bb);            // 784 x 16 CTAs
    agg_kernel<<<g1, 384>>>(m);

    mid_kernel<<<Bb, 256>>>();

    dim3 g3(Nn / RPB, Bb);      // 49 x 16 blocks, 16 rows each
    norm_kernel<<<g3, 512>>>(out);
}